// round 10
// baseline (speedup 1.0000x reference)
#include <cuda_runtime.h>
#include <cuda_fp16.h>

#define NATOMS 768
#define NM1 767
#define NEDGE (NATOMS * NM1)
#define DIM 64
#define NC 50
#define NCONV 3
#define ISLICE 64           // 12 source slices per destination
#define RTAB 2048
#define DSCALE (2047.0f / 5.0f)
#define DSTEP  (5.0f / 2047.0f)

// -------- scratch (device globals; no runtime allocation) --------
__device__ float  g_h[NATOMS * DIM];
__device__ __half g_nwH[NATOMS * DIM];
__device__ float  g_agg[NATOMS * DIM];
__device__ float  g_ha[NATOMS];
// fp16 lerp tables, packed per (row, lane) as 4 halfs:
// conv:    [r][l] = { e_r[2l], e_r[2l+1], e_{r+1}[2l], e_{r+1}[2l+1] }
// readout: [r][l] = { g_r[l],  g_r[l+32], g_{r+1}[l],  g_{r+1}[l+32] }
__device__ __half g_tabH[NCONV][RTAB * 32 * 4];   // 1.5 MB total
__device__ __half g_roH[RTAB * 32 * 4];           // 0.5 MB

__device__ __forceinline__ float sp05(float x) {
    float bx = 0.5f * x;
    return (bx > 14.0f) ? x : 2.0f * log1pf(__expf(bx));
}

// ================= merged table builder =================
// grid (RTAB, NCONV+1): y<NCONV -> conv filter layer y; y==NCONV -> readout table
__global__ __launch_bounds__(64) void k_build(
    const float* __restrict__ pw1_all, const float* __restrict__ pb1_all,
    const float* __restrict__ pw2_all, const float* __restrict__ pb2_all,
    const float* __restrict__ ro_w1)
{
    int r = blockIdx.x, sel = blockIdx.y, t = threadIdx.x;
    float d = (float)r * DSTEP;

    __shared__ float srbf[NC];
    __shared__ float st[DIM];
    if (t < NC) {
        float x = d - (float)t * (5.0f / 49.0f);
        srbf[t] = __expf(-(49.0f / 5.0f) * x * x);
    }
    __syncthreads();

    if (sel < NCONV) {
        const float* pw1 = pw1_all + sel * NC * DIM;
        const float* pw2 = pw2_all + sel * DIM * DIM;
        float a = pb1_all[sel * DIM + t];
#pragma unroll
        for (int k = 0; k < NC; k++) a = fmaf(srbf[k], pw1[k * DIM + t], a);
        st[t] = sp05(a);
        __syncthreads();
        float e = pb2_all[sel * DIM + t];
#pragma unroll
        for (int k = 0; k < DIM; k++) e = fmaf(st[k], pw2[k * DIM + t], e);

        __half he = __float2half_rn(e);
        __half* tab = g_tabH[sel];
        int l = t >> 1, c = t & 1;
        tab[(r * 32 + l) * 4 + c] = he;                       // row r endpoint
        if (r > 0) tab[((r - 1) * 32 + l) * 4 + 2 + c] = he;  // row r-1's r+1 endpoint
    } else {
        float g = 0.f;
#pragma unroll
        for (int k = 0; k < NC; k++) g = fmaf(srbf[k], ro_w1[(2 + k) * DIM + t], g);
        __half hg = __float2half_rn(g);
        int l = t & 31, hi = t >> 5;
        g_roH[(r * 32 + l) * 4 + hi] = hg;
        if (r > 0) g_roH[((r - 1) * 32 + l) * 4 + 2 + hi] = hg;
    }
}

// ================= node kernels =================
__device__ __forceinline__ float dot64_sm(const float* __restrict__ s,
                                          const float* __restrict__ W, int t, float bias) {
    const float4* s4 = (const float4*)s;
    float a0 = bias, a1 = 0.f, a2 = 0.f, a3 = 0.f;
#pragma unroll
    for (int k = 0; k < 16; k++) {
        float4 v = s4[k];
        a0 = fmaf(v.x, W[(4 * k + 0) * DIM + t], a0);
        a1 = fmaf(v.y, W[(4 * k + 1) * DIM + t], a1);
        a2 = fmaf(v.z, W[(4 * k + 2) * DIM + t], a2);
        a3 = fmaf(v.w, W[(4 * k + 3) * DIM + t], a3);
    }
    return (a0 + a1) + (a2 + a3);
}

__global__ __launch_bounds__(64) void k_node_first(
    const int* __restrict__ at, const float* __restrict__ emb,
    const float* __restrict__ W)
{
    int n = blockIdx.x, t = threadIdx.x;
    __shared__ float sh[DIM];
    float h = emb[at[n] * DIM + t];
    g_h[n * DIM + t] = h;
    sh[t] = h;
    __syncthreads();
    g_nwH[n * DIM + t] = __float2half_rn(dot64_sm(sh, W, t, 0.f));
    g_agg[n * DIM + t] = 0.f;
}

__global__ __launch_bounds__(64) void k_node_mid(
    const float* __restrict__ qw1, const float* __restrict__ qb1,
    const float* __restrict__ qw2, const float* __restrict__ qb2,
    const float* __restrict__ Wnext)
{
    int n = blockIdx.x, t = threadIdx.x;
    __shared__ float sa[DIM], st[DIM], sh[DIM];
    sa[t] = g_agg[n * DIM + t];
    __syncthreads();
    st[t] = sp05(dot64_sm(sa, qw1, t, qb1[t]));
    __syncthreads();
    float u = dot64_sm(st, qw2, t, qb2[t]);
    float h = g_h[n * DIM + t] + u;
    g_h[n * DIM + t] = h;
    sh[t] = h;
    __syncthreads();
    g_nwH[n * DIM + t] = __float2half_rn(dot64_sm(sh, Wnext, t, 0.f));
    g_agg[n * DIM + t] = 0.f;
}

__global__ __launch_bounds__(64) void k_node_last(
    const float* __restrict__ qw1, const float* __restrict__ qb1,
    const float* __restrict__ qw2, const float* __restrict__ qb2,
    const float* __restrict__ auw1, const float* __restrict__ aub1,
    const float* __restrict__ auw2, const float* __restrict__ aub2)
{
    int n = blockIdx.x, t = threadIdx.x;
    __shared__ float sa[DIM], st[DIM], sh[DIM], red[DIM];
    sa[t] = g_agg[n * DIM + t];
    __syncthreads();
    st[t] = sp05(dot64_sm(sa, qw1, t, qb1[t]));
    __syncthreads();
    float h = g_h[n * DIM + t] + dot64_sm(st, qw2, t, qb2[t]);
    sh[t] = h;
    __syncthreads();
    float a = dot64_sm(sh, auw1, t, aub1[t]);
    float hid = ((a > 20.0f) ? a : log1pf(__expf(a))) - 0.69314718055994530942f;
    red[t] = hid * auw2[t];
    __syncthreads();
    if (t < 32) red[t] += red[t + 32];
    __syncthreads();
    if (t < 32) {
        float v = red[t];
#pragma unroll
        for (int o = 16; o; o >>= 1) v += __shfl_xor_sync(0xffffffffu, v, o);
        if (t == 0) g_ha[n] = v + aub2[0];
    }
}

// ================= fused LUT edge conv (fp16 tables, fp32 accum) =================
// grid (12 slices, 96 j-groups), 256 threads = 8 warps; warp w -> j = by*8+w.
// Staging precomputes the table row r and fraction f per edge (once per block,
// not per warp); per-edge gathers are one uint2 (table) + one uint (nw half2).
__global__ __launch_bounds__(256) void k_conv(const float* __restrict__ ed,
                                              const uint2* __restrict__ tab)
{
    __shared__ int   s_r[ISLICE * 8];
    __shared__ float s_f[ISLICE * 8];
    int lane = threadIdx.x & 31;
    int w = threadIdx.x >> 5;
    int jbase = blockIdx.y * 8;
    int j = jbase + w;
    int i0 = blockIdx.x * ISLICE;

    for (int idx = threadIdx.x; idx < ISLICE * 8; idx += 256) {
        int il = idx >> 3, jl = idx & 7;
        int i = i0 + il, jj = jbase + jl;
        int eidx = i * NM1 + jj - (jj > i ? 1 : 0);
        eidx = min(eidx, NEDGE - 1);               // i==j clamps; masked below
        float x = __ldg(ed + eidx) * DSCALE;
        int r = min((int)x, RTAB - 2);
        s_r[idx] = r;
        s_f[idx] = x - (float)r;
    }
    __syncthreads();

    const int*   srw = s_r + w;
    const float* sfw = s_f + w;
    float acc0 = 0.f, acc1 = 0.f;
#pragma unroll 2
    for (int ib = 0; ib < ISLICE; ib += 4) {
        int   r4[4];
        float f4[4];
#pragma unroll
        for (int k = 0; k < 4; k++) {
            r4[k] = srw[(ib + k) * 8];
            f4[k] = sfw[(ib + k) * 8];
        }
#pragma unroll
        for (int k = 0; k < 4; k++) {
            int i = i0 + ib + k;
            float f = f4[k];
            uint2 p  = __ldg(tab + r4[k] * 32 + lane);
            unsigned nv = __ldg((const unsigned*)(g_nwH + i * DIM) + lane);
            float2 A  = __half22float2(*(const __half2*)&p.x);
            float2 B  = __half22float2(*(const __half2*)&p.y);
            float2 nw = __half22float2(*(const __half2*)&nv);
            float ev0 = fmaf(f, B.x - A.x, A.x);
            float ev1 = fmaf(f, B.y - A.y, A.y);
            if (i != j) {
                acc0 = fmaf(nw.x, ev0, acc0);
                acc1 = fmaf(nw.y, ev1, acc1);
            }
        }
    }
    atomicAdd(&g_agg[j * DIM + 2 * lane], acc0);
    atomicAdd(&g_agg[j * DIM + 2 * lane + 1], acc1);
}

// ================= LUT readout (fp16 table) =================
__global__ __launch_bounds__(256) void k_readout(
    const float* __restrict__ ed,
    const float* __restrict__ w1, const float* __restrict__ b1,
    const float* __restrict__ w2, const float* __restrict__ b2,
    float2* __restrict__ out, int nwarps_total)
{
    int lane = threadIdx.x & 31;
    int gw = blockIdx.x * 8 + (threadIdx.x >> 5);
    int t0 = lane, t1 = lane + 32;

    float wsrc0 = w1[t0],        wdst0 = w1[DIM + t0];
    float wsrc1 = w1[t1],        wdst1 = w1[DIM + t1];
    float bb0 = b1[t0],          bb1 = b1[t1];
    float w200 = w2[t0 * 2],     w201 = w2[t0 * 2 + 1];
    float w210 = w2[t1 * 2],     w211 = w2[t1 * 2 + 1];
    float lb0 = b2[0],           lb1 = b2[1];
    const uint2* ro = (const uint2*)g_roH;

    for (int e = gw; e < NEDGE; e += nwarps_total) {
        int i = e / NM1;
        int jj = e - i * NM1;
        int j = jj + (jj >= i ? 1 : 0);
        float d = __ldg(&ed[e]);
        float hai = __ldg(&g_ha[i]);
        float haj = __ldg(&g_ha[j]);

        float x = d * DSCALE;
        int r = min((int)x, RTAB - 2);
        float f = x - (float)r;
        uint2 p = __ldg(ro + r * 32 + lane);
        float2 A = __half22float2(*(const __half2*)&p.x);   // (g_r[t0], g_r[t1])
        float2 B = __half22float2(*(const __half2*)&p.y);   // (g_r1[t0], g_r1[t1])
        float g0 = fmaf(f, B.x - A.x, A.x);
        float g1 = fmaf(f, B.y - A.y, A.y);

        float h0 = fmaxf(fmaf(hai, wsrc0, fmaf(haj, wdst0, bb0 + g0)), 0.f);
        float h1 = fmaxf(fmaf(hai, wsrc1, fmaf(haj, wdst1, bb1 + g1)), 0.f);
        float l0 = fmaf(h0, w200, h1 * w210);
        float l1 = fmaf(h0, w201, h1 * w211);
#pragma unroll
        for (int o = 16; o; o >>= 1) {
            l0 += __shfl_xor_sync(0xffffffffu, l0, o);
            l1 += __shfl_xor_sync(0xffffffffu, l1, o);
        }
        if (lane == 0) {
            l0 += lb0; l1 += lb1;
            float m = fmaxf(l0, l1);
            float e0 = __expf(l0 - m), e1 = __expf(l1 - m);
            float inv = 1.0f / (e0 + e1);
            out[e] = make_float2(e0 * inv, e1 * inv);
        }
    }
}

extern "C" void kernel_launch(void* const* d_in, const int* in_sizes, int n_in,
                              void* d_out, int out_size) {
    const int*   at   = (const int*)d_in[0];
    const float* ed   = (const float*)d_in[1];
    const float* emb  = (const float*)d_in[4];
    const float* w1   = (const float*)d_in[5];
    const float* pw1  = (const float*)d_in[6];
    const float* pb1  = (const float*)d_in[7];
    const float* pw2  = (const float*)d_in[8];
    const float* pb2  = (const float*)d_in[9];
    const float* qw1  = (const float*)d_in[10];
    const float* qb1  = (const float*)d_in[11];
    const float* qw2  = (const float*)d_in[12];
    const float* qb2  = (const float*)d_in[13];
    const float* auw1 = (const float*)d_in[14];
    const float* aub1 = (const float*)d_in[15];
    const float* auw2 = (const float*)d_in[16];
    const float* aub2 = (const float*)d_in[17];
    const float* row1 = (const float*)d_in[18];
    const float* rob1 = (const float*)d_in[19];
    const float* row2 = (const float*)d_in[20];
    const float* rob2 = (const float*)d_in[21];

    __half* tabh; cudaGetSymbolAddress((void**)&tabh, g_tabH);

    k_build<<<dim3(RTAB, NCONV + 1), DIM>>>(pw1, pb1, pw2, pb2, row1);

    k_node_first<<<NATOMS, DIM>>>(at, emb, w1);
    for (int l = 0; l < NCONV; l++) {
        k_conv<<<dim3(NATOMS / ISLICE, NATOMS / 8), 256>>>(
            ed, (const uint2*)(tabh + (size_t)l * RTAB * 32 * 4));
        if (l < NCONV - 1)
            k_node_mid<<<NATOMS, DIM>>>(qw1 + l * DIM * DIM, qb1 + l * DIM,
                                        qw2 + l * DIM * DIM, qb2 + l * DIM,
                                        w1 + (l + 1) * DIM * DIM);
    }
    k_node_last<<<NATOMS, DIM>>>(qw1 + 2 * DIM * DIM, qb1 + 2 * DIM,
                                 qw2 + 2 * DIM * DIM, qb2 + 2 * DIM,
                                 auw1, aub1, auw2, aub2);
    int blocks = 1184;
    k_readout<<<blocks, 256>>>(ed, row1, rob1, row2, rob2,
                               (float2*)d_out, blocks * 8);
}

// round 15
// speedup vs baseline: 1.0855x; 1.0855x over previous
#include <cuda_runtime.h>
#include <cuda_fp16.h>

#define NATOMS 768
#define NM1 767
#define NEDGE (NATOMS * NM1)
#define DIM 64
#define NC 50
#define NCONV 3
#define ISLICE 64
#define RTAB 2048
#define DSCALE (2047.0f / 5.0f)
#define DSTEP  (5.0f / 2047.0f)

// -------- scratch (device globals; no runtime allocation) --------
__device__ float  g_h[NATOMS * DIM];
__device__ __half g_nwH[NATOMS * DIM];
__device__ float  g_agg[NATOMS * DIM];
__device__ float  g_ha[NATOMS];
// fp16 lerp tables, packed per (row, lane) as 4 halfs:
// conv:    [r][l] = { e_r[2l], e_r[2l+1], e_{r+1}[2l], e_{r+1}[2l+1] }
// readout: [r][l] = { g_r[l],  g_r[l+32], g_{r+1}[l],  g_{r+1}[l+32] }
__device__ __half g_tabH[NCONV][RTAB * 32 * 4];
__device__ __half g_roH[RTAB * 32 * 4];

__device__ __forceinline__ float sp05(float x) {
    float bx = 0.5f * x;
    return (bx > 14.0f) ? x : 2.0f * log1pf(__expf(bx));
}

// 4-way k-split 64x64 matvec piece. 256 threads: t=tid&63 (out dim), q=tid>>6.
// Each thread: 16 coalesced LDGs + 16 FMA; smem 4-way reduce.
// Contains ONE barrier; result valid for tid<64. Caller must __syncthreads()
// after consuming before 'part' is reused.
__device__ __forceinline__ float mv64(const float* __restrict__ v,
                                      const float* __restrict__ W,
                                      int t, int q, float* part, int tid) {
    const float* vq = v + q * 16;
    const float* Wq = W + (q * 16) * DIM + t;
    float s0 = 0.f, s1 = 0.f, s2 = 0.f, s3 = 0.f;
#pragma unroll
    for (int kk = 0; kk < 16; kk += 4) {
        s0 = fmaf(vq[kk + 0], Wq[(kk + 0) * DIM], s0);
        s1 = fmaf(vq[kk + 1], Wq[(kk + 1) * DIM], s1);
        s2 = fmaf(vq[kk + 2], Wq[(kk + 2) * DIM], s2);
        s3 = fmaf(vq[kk + 3], Wq[(kk + 3) * DIM], s3);
    }
    part[tid] = (s0 + s1) + (s2 + s3);
    __syncthreads();
    float r = 0.f;
    if (tid < DIM) r = (part[t] + part[DIM + t]) + (part[2 * DIM + t] + part[3 * DIM + t]);
    return r;
}

// ================= prelude: tables + node_first, merged =================
// grid (RTAB, 5), 256 threads.
//   y<NCONV : conv table layer y, row x     y==NCONV : readout table row x
//   y==NCONV+1, x<NATOMS : node_first for atom x
__global__ __launch_bounds__(256) void k_prelude(
    const float* __restrict__ pw1_all, const float* __restrict__ pb1_all,
    const float* __restrict__ pw2_all, const float* __restrict__ pb2_all,
    const float* __restrict__ ro_w1,
    const int* __restrict__ at, const float* __restrict__ emb,
    const float* __restrict__ W0)
{
    int sel = blockIdx.y, bx = blockIdx.x;
    int tid = threadIdx.x, t = tid & 63, q = tid >> 6;
    __shared__ float sv[DIM];
    __shared__ float part[256];

    if (sel == NCONV + 1) {                       // ---- node_first ----
        if (bx >= NATOMS) return;
        int n = bx;
        if (tid < DIM) {
            float h = emb[at[n] * DIM + tid];
            g_h[n * DIM + tid] = h;
            sv[tid] = h;
            g_agg[n * DIM + tid] = 0.f;
        }
        __syncthreads();
        float nw = mv64(sv, W0, t, q, part, tid);
        if (tid < DIM) g_nwH[n * DIM + t] = __float2half_rn(nw);
        return;
    }

    // ---- table rows ----
    int r = bx;
    float d = (float)r * DSTEP;
    __shared__ float srbf[52];
    if (tid < 52) {
        float rb = 0.f;
        if (tid < NC) {
            float x = d - (float)tid * (5.0f / 49.0f);
            rb = __expf(-(49.0f / 5.0f) * x * x);
        }
        srbf[tid] = rb;
    }
    __syncthreads();

    if (sel < NCONV) {
        const float* pw1 = pw1_all + sel * NC * DIM;
        const float* pw2 = pw2_all + sel * DIM * DIM;
        // layer1: 50-dot, 13 k's per quadrant (guarded)
        float s = 0.f;
#pragma unroll
        for (int kk = 0; kk < 13; kk++) {
            int k = q * 13 + kk;
            if (k < NC) s = fmaf(srbf[k], pw1[k * DIM + t], s);
        }
        part[tid] = s;
        __syncthreads();
        if (tid < DIM)
            sv[t] = sp05((part[t] + part[DIM + t]) + (part[2 * DIM + t] + part[3 * DIM + t])
                         + pb1_all[sel * DIM + t]);
        __syncthreads();
        float e = mv64(sv, pw2, t, q, part, tid);
        if (tid < DIM) {
            __half he = __float2half_rn(e + pb2_all[sel * DIM + t]);
            __half* tab = g_tabH[sel];
            int l = t >> 1, c = t & 1;
            tab[(r * 32 + l) * 4 + c] = he;
            if (r > 0) tab[((r - 1) * 32 + l) * 4 + 2 + c] = he;
        }
    } else {                                      // readout table
        float s = 0.f;
#pragma unroll
        for (int kk = 0; kk < 13; kk++) {
            int k = q * 13 + kk;
            if (k < NC) s = fmaf(srbf[k], ro_w1[(2 + k) * DIM + t], s);
        }
        part[tid] = s;
        __syncthreads();
        if (tid < DIM) {
            float g = (part[t] + part[DIM + t]) + (part[2 * DIM + t] + part[3 * DIM + t]);
            __half hg = __float2half_rn(g);
            int l = t & 31, hi = t >> 5;
            g_roH[(r * 32 + l) * 4 + hi] = hg;
            if (r > 0) g_roH[((r - 1) * 32 + l) * 4 + 2 + hi] = hg;
        }
    }
}

// ================= node mid / last (256 threads, k-split matvecs) =================
__global__ __launch_bounds__(256) void k_node_mid(
    const float* __restrict__ qw1, const float* __restrict__ qb1,
    const float* __restrict__ qw2, const float* __restrict__ qb2,
    const float* __restrict__ Wnext)
{
    int n = blockIdx.x;
    int tid = threadIdx.x, t = tid & 63, q = tid >> 6;
    __shared__ float sv[DIM], st[DIM], part[256];

    if (tid < DIM) sv[tid] = g_agg[n * DIM + tid];
    __syncthreads();
    float a = mv64(sv, qw1, t, q, part, tid);
    if (tid < DIM) st[t] = sp05(a + qb1[t]);
    __syncthreads();
    float u = mv64(st, qw2, t, q, part, tid);
    if (tid < DIM) {
        float h = g_h[n * DIM + t] + u + qb2[t];
        g_h[n * DIM + t] = h;
        sv[t] = h;
    }
    __syncthreads();
    float nw = mv64(sv, Wnext, t, q, part, tid);
    if (tid < DIM) {
        g_nwH[n * DIM + t] = __float2half_rn(nw);
        g_agg[n * DIM + t] = 0.f;
    }
}

__global__ __launch_bounds__(256) void k_node_last(
    const float* __restrict__ qw1, const float* __restrict__ qb1,
    const float* __restrict__ qw2, const float* __restrict__ qb2,
    const float* __restrict__ auw1, const float* __restrict__ aub1,
    const float* __restrict__ auw2, const float* __restrict__ aub2)
{
    int n = blockIdx.x;
    int tid = threadIdx.x, t = tid & 63, q = tid >> 6;
    __shared__ float sv[DIM], st[DIM], part[256], red[DIM];

    if (tid < DIM) sv[tid] = g_agg[n * DIM + tid];
    __syncthreads();
    float a = mv64(sv, qw1, t, q, part, tid);
    if (tid < DIM) st[t] = sp05(a + qb1[t]);
    __syncthreads();
    float u = mv64(st, qw2, t, q, part, tid);
    if (tid < DIM) sv[t] = g_h[n * DIM + t] + u + qb2[t];
    __syncthreads();
    float aa = mv64(sv, auw1, t, q, part, tid);
    if (tid < DIM) {
        float x = aa + aub1[t];
        float hid = ((x > 20.0f) ? x : log1pf(__expf(x))) - 0.69314718055994530942f;
        red[t] = hid * auw2[t];
    }
    __syncthreads();
    if (tid < 32) {
        float v = red[tid] + red[tid + 32];
#pragma unroll
        for (int o = 16; o; o >>= 1) v += __shfl_xor_sync(0xffffffffu, v, o);
        if (tid == 0) g_ha[n] = v + aub2[0];
    }
}

// ================= fused LUT edge conv (fp16 tables, fp32 accum) =================
__global__ __launch_bounds__(256) void k_conv(const float* __restrict__ ed,
                                              const uint2* __restrict__ tab)
{
    __shared__ int   s_r[ISLICE * 8];
    __shared__ float s_f[ISLICE * 8];
    int lane = threadIdx.x & 31;
    int w = threadIdx.x >> 5;
    int jbase = blockIdx.y * 8;
    int j = jbase + w;
    int i0 = blockIdx.x * ISLICE;

    for (int idx = threadIdx.x; idx < ISLICE * 8; idx += 256) {
        int il = idx >> 3, jl = idx & 7;
        int i = i0 + il, jj = jbase + jl;
        int eidx = i * NM1 + jj - (jj > i ? 1 : 0);
        eidx = min(eidx, NEDGE - 1);               // i==j clamps; masked below
        float x = __ldg(ed + eidx) * DSCALE;
        int r = min((int)x, RTAB - 2);
        s_r[idx] = r;
        s_f[idx] = x - (float)r;
    }
    __syncthreads();

    const int*   srw = s_r + w;
    const float* sfw = s_f + w;
    float acc0 = 0.f, acc1 = 0.f;
#pragma unroll 2
    for (int ib = 0; ib < ISLICE; ib += 4) {
        int   r4[4];
        float f4[4];
#pragma unroll
        for (int k = 0; k < 4; k++) {
            r4[k] = srw[(ib + k) * 8];
            f4[k] = sfw[(ib + k) * 8];
        }
#pragma unroll
        for (int k = 0; k < 4; k++) {
            int i = i0 + ib + k;
            float f = f4[k];
            uint2 p  = __ldg(tab + r4[k] * 32 + lane);
            unsigned nv = __ldg((const unsigned*)(g_nwH + i * DIM) + lane);
            float2 A  = __half22float2(*(const __half2*)&p.x);
            float2 B  = __half22float2(*(const __half2*)&p.y);
            float2 nw = __half22float2(*(const __half2*)&nv);
            float ev0 = fmaf(f, B.x - A.x, A.x);
            float ev1 = fmaf(f, B.y - A.y, A.y);
            if (i != j) {
                acc0 = fmaf(nw.x, ev0, acc0);
                acc1 = fmaf(nw.y, ev1, acc1);
            }
        }
    }
    atomicAdd(&g_agg[j * DIM + 2 * lane], acc0);
    atomicAdd(&g_agg[j * DIM + 2 * lane + 1], acc1);
}

// ================= LUT readout (fp16 table) =================
__global__ __launch_bounds__(256) void k_readout(
    const float* __restrict__ ed,
    const float* __restrict__ w1, const float* __restrict__ b1,
    const float* __restrict__ w2, const float* __restrict__ b2,
    float2* __restrict__ out, int nwarps_total)
{
    int lane = threadIdx.x & 31;
    int gw = blockIdx.x * 8 + (threadIdx.x >> 5);
    int t0 = lane, t1 = lane + 32;

    float wsrc0 = w1[t0],        wdst0 = w1[DIM + t0];
    float wsrc1 = w1[t1],        wdst1 = w1[DIM + t1];
    float bb0 = b1[t0],          bb1 = b1[t1];
    float w200 = w2[t0 * 2],     w201 = w2[t0 * 2 + 1];
    float w210 = w2[t1 * 2],     w211 = w2[t1 * 2 + 1];
    float lb0 = b2[0],           lb1 = b2[1];
    const uint2* ro = (const uint2*)g_roH;

    for (int e = gw; e < NEDGE; e += nwarps_total) {
        int i = e / NM1;
        int jj = e - i * NM1;
        int j = jj + (jj >= i ? 1 : 0);
        float d = __ldg(&ed[e]);
        float hai = __ldg(&g_ha[i]);
        float haj = __ldg(&g_ha[j]);

        float x = d * DSCALE;
        int r = min((int)x, RTAB - 2);
        float f = x - (float)r;
        uint2 p = __ldg(ro + r * 32 + lane);
        float2 A = __half22float2(*(const __half2*)&p.x);
        float2 B = __half22float2(*(const __half2*)&p.y);
        float g0 = fmaf(f, B.x - A.x, A.x);
        float g1 = fmaf(f, B.y - A.y, A.y);

        float h0 = fmaxf(fmaf(hai, wsrc0, fmaf(haj, wdst0, bb0 + g0)), 0.f);
        float h1 = fmaxf(fmaf(hai, wsrc1, fmaf(haj, wdst1, bb1 + g1)), 0.f);
        float l0 = fmaf(h0, w200, h1 * w210);
        float l1 = fmaf(h0, w201, h1 * w211);
#pragma unroll
        for (int o = 16; o; o >>= 1) {
            l0 += __shfl_xor_sync(0xffffffffu, l0, o);
            l1 += __shfl_xor_sync(0xffffffffu, l1, o);
        }
        if (lane == 0) {
            l0 += lb0; l1 += lb1;
            float m = fmaxf(l0, l1);
            float e0 = __expf(l0 - m), e1 = __expf(l1 - m);
            float inv = 1.0f / (e0 + e1);
            out[e] = make_float2(e0 * inv, e1 * inv);
        }
    }
}

extern "C" void kernel_launch(void* const* d_in, const int* in_sizes, int n_in,
                              void* d_out, int out_size) {
    const int*   at   = (const int*)d_in[0];
    const float* ed   = (const float*)d_in[1];
    const float* emb  = (const float*)d_in[4];
    const float* w1   = (const float*)d_in[5];
    const float* pw1  = (const float*)d_in[6];
    const float* pb1  = (const float*)d_in[7];
    const float* pw2  = (const float*)d_in[8];
    const float* pb2  = (const float*)d_in[9];
    const float* qw1  = (const float*)d_in[10];
    const float* qb1  = (const float*)d_in[11];
    const float* qw2  = (const float*)d_in[12];
    const float* qb2  = (const float*)d_in[13];
    const float* auw1 = (const float*)d_in[14];
    const float* aub1 = (const float*)d_in[15];
    const float* auw2 = (const float*)d_in[16];
    const float* aub2 = (const float*)d_in[17];
    const float* row1 = (const float*)d_in[18];
    const float* rob1 = (const float*)d_in[19];
    const float* row2 = (const float*)d_in[20];
    const float* rob2 = (const float*)d_in[21];

    __half* tabh; cudaGetSymbolAddress((void**)&tabh, g_tabH);

    k_prelude<<<dim3(RTAB, NCONV + 2), 256>>>(pw1, pb1, pw2, pb2, row1, at, emb, w1);

    for (int l = 0; l < NCONV; l++) {
        k_conv<<<dim3(NATOMS / ISLICE, NATOMS / 8), 256>>>(
            ed, (const uint2*)(tabh + (size_t)l * RTAB * 32 * 4));
        if (l < NCONV - 1)
            k_node_mid<<<NATOMS, 256>>>(qw1 + l * DIM * DIM, qb1 + l * DIM,
                                        qw2 + l * DIM * DIM, qb2 + l * DIM,
                                        w1 + (l + 1) * DIM * DIM);
    }
    k_node_last<<<NATOMS, 256>>>(qw1 + 2 * DIM * DIM, qb1 + 2 * DIM,
                                 qw2 + 2 * DIM * DIM, qb2 + 2 * DIM,
                                 auw1, aub1, auw2, aub2);
    int blocks = 1184;
    k_readout<<<blocks, 256>>>(ed, row1, rob1, row2, rob2,
                               (float2*)d_out, blocks * 8);
}